// round 11
// baseline (speedup 1.0000x reference)
#include <cuda_runtime.h>
#include <cuda_bf16.h>

// SpatialTransformer: B=16, H=W=384, C=32, fp32, NHWC.
// R5 winner body + per-WARP inline setup (no barrier, no smem):
// each warp redundantly computes the 6 batch coefficients; the 4 IEEE
// divisions are lane-parallel (lanes 0/1 carry different numerators through
// one div sequence, results shfl-broadcast). Single kernel launch.
// 1D grid, row-major block order. Block = 64-pixel row segment.
// 8 threads/pixel; each thread handles TWO pixels (j, j+32).

#define B_ 16
#define H_ 384
#define W_ 384
#define C_ 32
#define CV_ (C_/4)   // float4 groups per pixel = 8

struct Tap {
    int ia, ib, ic, id;
    float wa, wb, wc, wd;
};

__device__ __forceinline__ Tap make_tap(int j, float ys,
                                        float m00, float m01, float cy,
                                        float m10, float m11, float cx,
                                        int base, int cg)
{
    const float STEP = 2.0f / 383.0f;
    float xs = __fadd_rn(__fmul_rn((float)j, STEP), -1.0f);

    float gx = __fadd_rn(__fmaf_rn(m01, ys, __fmul_rn(m00, xs)), cy);
    float gy = __fadd_rn(__fmaf_rn(m11, ys, __fmul_rn(m10, xs)), cx);

    float x = __fmul_rn(__fmul_rn(__fadd_rn(gx, 1.0f), 384.0f), 0.5f);
    float y = __fmul_rn(__fmul_rn(__fadd_rn(gy, 1.0f), 384.0f), 0.5f);

    int x0 = (int)floorf(x);
    int y0 = (int)floorf(y);
    int x1 = x0 + 1;
    int y1 = y0 + 1;
    x0 = min(max(x0, 0), W_ - 1);
    x1 = min(max(x1, 0), W_ - 1);
    y0 = min(max(y0, 0), H_ - 1);
    y1 = min(max(y1, 0), H_ - 1);
    float x0f = (float)x0, x1f = (float)x1;
    float y0f = (float)y0, y1f = (float)y1;

    float wxa = __fsub_rn(x1f, x);
    float wxc = __fsub_rn(x, x0f);
    float wya = __fsub_rn(y1f, y);
    float wyb = __fsub_rn(y, y0f);

    Tap t;
    t.wa = __fmul_rn(wxa, wya);
    t.wb = __fmul_rn(wxa, wyb);
    t.wc = __fmul_rn(wxc, wya);
    t.wd = __fmul_rn(wxc, wyb);
    t.ia = base + (y0 * W_ + x0) * CV_ + cg;
    t.ib = base + (y1 * W_ + x0) * CV_ + cg;
    t.ic = base + (y0 * W_ + x1) * CV_ + cg;
    t.id = base + (y1 * W_ + x1) * CV_ + cg;
    return t;
}

// blocks: B*H*(W/64) = 16*384*6 = 36864, row-major (batch, row, tile)
__global__ __launch_bounds__(256)
void st_bilinear_kernel(const float4* __restrict__ img,
                        const float*  __restrict__ theta,
                        float4* __restrict__ out)
{
    const int tid = threadIdx.x;
    const int blk = blockIdx.x;

    const int tile = blk % 6;                 // 64-px column tile
    const int bi   = blk / 6;                 // b*384 + i
    const int i    = bi % H_;
    const int b    = bi / H_;

    // ---- per-warp theta adjustment (identical IEEE sequence, no barrier) ----
    const int lane = tid & 31;
    const float* t = theta + b * 6;
    float a00 = __ldg(t + 0), a01 = __ldg(t + 1), a02 = __ldg(t + 2);
    float a10 = __ldg(t + 3), a11 = __ldg(t + 4), a12 = __ldg(t + 5);

    bool piv = fabsf(a10) > fabsf(a00);
    float b00 = piv ? a10 : a00;
    float b01 = piv ? a11 : a01;
    float b10 = piv ? a00 : a10;
    float b11 = piv ? a01 : a11;

    float rr  = __frcp_rn(b00);
    float l   = __fmul_rn(b10, rr);
    float u11 = __fsub_rn(b11, __fmul_rn(l, b01));

    // div round 1 (denominator u11): lane0 -> x10 = -l/u11, lane1 -> x11 = 1/u11
    float num1 = (lane == 0) ? -l : 1.0f;
    float q1   = __fdiv_rn(num1, u11);
    float x10  = __shfl_sync(0xffffffffu, q1, 0);
    float x11  = __shfl_sync(0xffffffffu, q1, 1);

    // div round 2 (denominator b00):
    //   lane0 -> x00 = (1 - x10*b01)/b00, lane1 -> x01 = -(x11*b01)/b00
    float num2 = (lane == 0) ? __fsub_rn(1.0f, __fmul_rn(x10, b01))
                             : -__fmul_rn(x11, b01);
    float q2   = __fdiv_rn(num2, b00);
    float x00  = __shfl_sync(0xffffffffu, q2, 0);
    float x01  = __shfl_sync(0xffffffffu, q2, 1);

    float m00 = piv ? x01 : x00;
    float m01 = piv ? x00 : x01;
    float m10 = piv ? x11 : x10;
    float m11 = piv ? x10 : x11;

    float xc = __fmul_rn(__fadd_rn(-a02, 0.5f), m00);
    float yc = __fmul_rn(__fadd_rn(-a12, 0.5f), m11);
    float cy = __fsub_rn(__fmul_rn(yc, 2.0f), 1.0f);
    float cx = __fsub_rn(__fmul_rn(xc, 2.0f), 1.0f);

    const int j0 = tile * 64 + (tid >> 3);    // first pixel column
    const int j1 = j0 + 32;                   // second pixel column
    const int cg = tid & 7;                   // float4 channel group

    const float STEP = 2.0f / 383.0f;
    float ys = __fadd_rn(__fmul_rn((float)i, STEP), -1.0f);

    const int base = b * (H_ * W_ * CV_);

    Tap t0 = make_tap(j0, ys, m00, m01, cy, m10, m11, cx, base, cg);
    Tap t1 = make_tap(j1, ys, m00, m01, cy, m10, m11, cx, base, cg);

    // 8 front-batched, fully-coalesced LDG.128 (4 pixels/warp per tap)
    float4 a0 = __ldg(img + t0.ia);
    float4 b0 = __ldg(img + t0.ib);
    float4 c0 = __ldg(img + t0.ic);
    float4 d0 = __ldg(img + t0.id);
    float4 a1 = __ldg(img + t1.ia);
    float4 b1 = __ldg(img + t1.ib);
    float4 c1 = __ldg(img + t1.ic);
    float4 d1 = __ldg(img + t1.id);

#define BLEND(T,A,B,C,D,f) \
    __fadd_rn(__fadd_rn(__fadd_rn(__fmul_rn((T).wa, (A).f), __fmul_rn((T).wb, (B).f)), \
                         __fmul_rn((T).wc, (C).f)), __fmul_rn((T).wd, (D).f))

    float4 r0, r1;
    r0.x = BLEND(t0, a0, b0, c0, d0, x);
    r0.y = BLEND(t0, a0, b0, c0, d0, y);
    r0.z = BLEND(t0, a0, b0, c0, d0, z);
    r0.w = BLEND(t0, a0, b0, c0, d0, w);
    r1.x = BLEND(t1, a1, b1, c1, d1, x);
    r1.y = BLEND(t1, a1, b1, c1, d1, y);
    r1.z = BLEND(t1, a1, b1, c1, d1, z);
    r1.w = BLEND(t1, a1, b1, c1, d1, w);
#undef BLEND

    const int orow = base + (i * W_) * CV_ + cg;
    out[orow + j0 * CV_] = r0;     // plain cached stores
    out[orow + j1 * CV_] = r1;
}

extern "C" void kernel_launch(void* const* d_in, const int* in_sizes, int n_in,
                              void* d_out, int out_size)
{
    const float4* img   = (const float4*)d_in[0];   // images: (16,384,384,32) f32
    const float*  theta = (const float*)d_in[1];    // theta:  (16,6) f32
    float4* out = (float4*)d_out;

    const int blocks = B_ * H_ * (W_ / 64);   // 36864
    st_bilinear_kernel<<<blocks, 256>>>(img, theta, out);
}

// round 12
// speedup vs baseline: 1.0600x; 1.0600x over previous
#include <cuda_runtime.h>
#include <cuda_bf16.h>

// SpatialTransformer: B=16, H=W=384, C=32, fp32, NHWC.
// PERSISTENT kernel: grid = 148*8 CTAs (one wave), grid-stride over all
// 36864 tiles (64-px row segments). Per-CTA setup runs ONCE: lanes 0..15
// compute all 16 batches' coefficients (one SIMT div sequence total) into
// smem; loop body is the R5 winner verbatim (8 threads/pixel, 2 px/thread,
// 8 front-batched LDG.128, plain STG.128). regs capped at 32 via
// __launch_bounds__(256, 8) to stay below the RF occupancy cliff.

#define B_ 16
#define H_ 384
#define W_ 384
#define C_ 32
#define CV_ (C_/4)   // float4 groups per pixel = 8

#define NTILES (B_ * H_ * (W_ / 64))   // 36864
#define GRIDSZ (148 * 8)               // 1184 = one full wave

struct Tap {
    int ia, ib, ic, id;
    float wa, wb, wc, wd;
};

__device__ __forceinline__ Tap make_tap(int j, float ys,
                                        float m00, float m01, float cy,
                                        float m10, float m11, float cx,
                                        int base, int cg)
{
    const float STEP = 2.0f / 383.0f;
    float xs = __fadd_rn(__fmul_rn((float)j, STEP), -1.0f);

    float gx = __fadd_rn(__fmaf_rn(m01, ys, __fmul_rn(m00, xs)), cy);
    float gy = __fadd_rn(__fmaf_rn(m11, ys, __fmul_rn(m10, xs)), cx);

    float x = __fmul_rn(__fmul_rn(__fadd_rn(gx, 1.0f), 384.0f), 0.5f);
    float y = __fmul_rn(__fmul_rn(__fadd_rn(gy, 1.0f), 384.0f), 0.5f);

    int x0 = (int)floorf(x);
    int y0 = (int)floorf(y);
    int x1 = x0 + 1;
    int y1 = y0 + 1;
    x0 = min(max(x0, 0), W_ - 1);
    x1 = min(max(x1, 0), W_ - 1);
    y0 = min(max(y0, 0), H_ - 1);
    y1 = min(max(y1, 0), H_ - 1);
    float x0f = (float)x0, x1f = (float)x1;
    float y0f = (float)y0, y1f = (float)y1;

    float wxa = __fsub_rn(x1f, x);
    float wxc = __fsub_rn(x, x0f);
    float wya = __fsub_rn(y1f, y);
    float wyb = __fsub_rn(y, y0f);

    Tap t;
    t.wa = __fmul_rn(wxa, wya);
    t.wb = __fmul_rn(wxa, wyb);
    t.wc = __fmul_rn(wxc, wya);
    t.wd = __fmul_rn(wxc, wyb);
    t.ia = base + (y0 * W_ + x0) * CV_ + cg;
    t.ib = base + (y1 * W_ + x0) * CV_ + cg;
    t.ic = base + (y0 * W_ + x1) * CV_ + cg;
    t.id = base + (y1 * W_ + x1) * CV_ + cg;
    return t;
}

__global__ __launch_bounds__(256, 8)
void st_bilinear_kernel(const float4* __restrict__ img,
                        const float*  __restrict__ theta,
                        float4* __restrict__ out)
{
    __shared__ float scoef[B_][6];

    const int tid = threadIdx.x;

    // ---- per-CTA setup: lanes 0..15 each handle one batch (one SIMT div
    //      sequence covers all 16 batches). Identical IEEE op sequence. ----
    if (tid < B_) {
        const float* t = theta + tid * 6;
        float a00 = __ldg(t + 0), a01 = __ldg(t + 1), a02 = __ldg(t + 2);
        float a10 = __ldg(t + 3), a11 = __ldg(t + 4), a12 = __ldg(t + 5);

        bool piv = fabsf(a10) > fabsf(a00);
        float b00 = piv ? a10 : a00;
        float b01 = piv ? a11 : a01;
        float b10 = piv ? a00 : a10;
        float b11 = piv ? a01 : a11;

        float rr  = __frcp_rn(b00);
        float l   = __fmul_rn(b10, rr);
        float u11 = __fsub_rn(b11, __fmul_rn(l, b01));

        float x10 = __fdiv_rn(-l, u11);
        float x00 = __fdiv_rn(__fsub_rn(1.0f, __fmul_rn(x10, b01)), b00);
        float x11 = __fdiv_rn(1.0f, u11);
        float x01 = __fdiv_rn(-__fmul_rn(x11, b01), b00);

        float m00 = piv ? x01 : x00;
        float m01 = piv ? x00 : x01;
        float m10 = piv ? x11 : x10;
        float m11 = piv ? x10 : x11;

        float xc = __fmul_rn(__fadd_rn(-a02, 0.5f), m00);
        float yc = __fmul_rn(__fadd_rn(-a12, 0.5f), m11);

        scoef[tid][0] = m00;
        scoef[tid][1] = m01;
        scoef[tid][2] = __fsub_rn(__fmul_rn(yc, 2.0f), 1.0f);   // cy
        scoef[tid][3] = m10;
        scoef[tid][4] = m11;
        scoef[tid][5] = __fsub_rn(__fmul_rn(xc, 2.0f), 1.0f);   // cx
    }
    __syncthreads();

    const int px = tid >> 3;        // pixel-in-tile (0..31)
    const int cg = tid & 7;         // float4 channel group
    const float STEP = 2.0f / 383.0f;

    // ---- persistent grid-stride loop over tiles ----
    for (int blk = blockIdx.x; blk < NTILES; blk += GRIDSZ) {
        const int tile = blk % 6;             // 64-px column tile
        const int bi   = blk / 6;             // b*384 + i
        const int i    = bi % H_;
        const int b    = bi / H_;

        const int j0 = tile * 64 + px;
        const int j1 = j0 + 32;

        float m00 = scoef[b][0], m01 = scoef[b][1], cy = scoef[b][2];
        float m10 = scoef[b][3], m11 = scoef[b][4], cx = scoef[b][5];

        float ys = __fadd_rn(__fmul_rn((float)i, STEP), -1.0f);

        const int base = b * (H_ * W_ * CV_);

        Tap t0 = make_tap(j0, ys, m00, m01, cy, m10, m11, cx, base, cg);
        Tap t1 = make_tap(j1, ys, m00, m01, cy, m10, m11, cx, base, cg);

        // 8 front-batched, fully-coalesced LDG.128 (4 pixels/warp per tap)
        float4 a0 = __ldg(img + t0.ia);
        float4 b0 = __ldg(img + t0.ib);
        float4 c0 = __ldg(img + t0.ic);
        float4 d0 = __ldg(img + t0.id);
        float4 a1 = __ldg(img + t1.ia);
        float4 b1 = __ldg(img + t1.ib);
        float4 c1 = __ldg(img + t1.ic);
        float4 d1 = __ldg(img + t1.id);

#define BLEND(T,A,B,C,D,f) \
    __fadd_rn(__fadd_rn(__fadd_rn(__fmul_rn((T).wa, (A).f), __fmul_rn((T).wb, (B).f)), \
                         __fmul_rn((T).wc, (C).f)), __fmul_rn((T).wd, (D).f))

        float4 r0, r1;
        r0.x = BLEND(t0, a0, b0, c0, d0, x);
        r0.y = BLEND(t0, a0, b0, c0, d0, y);
        r0.z = BLEND(t0, a0, b0, c0, d0, z);
        r0.w = BLEND(t0, a0, b0, c0, d0, w);
        r1.x = BLEND(t1, a1, b1, c1, d1, x);
        r1.y = BLEND(t1, a1, b1, c1, d1, y);
        r1.z = BLEND(t1, a1, b1, c1, d1, z);
        r1.w = BLEND(t1, a1, b1, c1, d1, w);
#undef BLEND

        const int orow = base + (i * W_) * CV_ + cg;
        out[orow + j0 * CV_] = r0;   // plain cached stores
        out[orow + j1 * CV_] = r1;
    }
}

extern "C" void kernel_launch(void* const* d_in, const int* in_sizes, int n_in,
                              void* d_out, int out_size)
{
    const float4* img   = (const float4*)d_in[0];   // images: (16,384,384,32) f32
    const float*  theta = (const float*)d_in[1];    // theta:  (16,6) f32
    float4* out = (float4*)d_out;

    st_bilinear_kernel<<<GRIDSZ, 256>>>(img, theta, out);
}

// round 13
// speedup vs baseline: 1.1553x; 1.0899x over previous
#include <cuda_runtime.h>
#include <cuda_bf16.h>

// SpatialTransformer: B=16, H=W=384, C=32, fp32, NHWC.
// R5 winner (two kernels) + PDL: the main kernel launches while the setup
// kernel is still running; it does theta-independent prologue work, then
// griddepcontrol.wait before reading the coefficients.
// Main body byte-identical to R5: 1D grid, row-major; block = 64-px row
// segment; 8 threads/pixel, 2 px/thread; 8 front-batched LDG.128; STG.128.

#define B_ 16
#define H_ 384
#define W_ 384
#define C_ 32
#define CV_ (C_/4)   // float4 groups per pixel = 8

__device__ float g_coef[B_][8];   // m00, m01, cy, m10, m11, cx

// ---- per-batch theta adjustment: mimic jnp.linalg.inv (sgetrf+strsm) exactly ----
__global__ void st_setup_kernel(const float* __restrict__ theta)
{
    int b = threadIdx.x;
    if (b < B_) {
        const float* t = theta + b * 6;
        float a00 = t[0], a01 = t[1], a02 = t[2];
        float a10 = t[3], a11 = t[4], a12 = t[5];

        bool piv = fabsf(a10) > fabsf(a00);
        float b00 = piv ? a10 : a00;
        float b01 = piv ? a11 : a01;
        float b10 = piv ? a00 : a10;
        float b11 = piv ? a01 : a11;

        float r   = __frcp_rn(b00);
        float l   = __fmul_rn(b10, r);
        float u11 = __fsub_rn(b11, __fmul_rn(l, b01));

        float x10 = __fdiv_rn(-l, u11);
        float x00 = __fdiv_rn(__fsub_rn(1.0f, __fmul_rn(x10, b01)), b00);
        float x11 = __fdiv_rn(1.0f, u11);
        float x01 = __fdiv_rn(-__fmul_rn(x11, b01), b00);

        float m00 = piv ? x01 : x00;
        float m01 = piv ? x00 : x01;
        float m10 = piv ? x11 : x10;
        float m11 = piv ? x10 : x11;

        float xc = __fmul_rn(__fadd_rn(-a02, 0.5f), m00);
        float yc = __fmul_rn(__fadd_rn(-a12, 0.5f), m11);
        float cy = __fsub_rn(__fmul_rn(yc, 2.0f), 1.0f);
        float cx = __fsub_rn(__fmul_rn(xc, 2.0f), 1.0f);

        g_coef[b][0] = m00; g_coef[b][1] = m01; g_coef[b][2] = cy;
        g_coef[b][3] = m10; g_coef[b][4] = m11; g_coef[b][5] = cx;
    }
    __syncthreads();
    __threadfence();                                   // make g_coef visible device-wide
    asm volatile("griddepcontrol.launch_dependents;"); // release dependent kernel
}

struct Tap {
    int ia, ib, ic, id;
    float wa, wb, wc, wd;
};

__device__ __forceinline__ Tap make_tap(int j, float ys,
                                        float m00, float m01, float cy,
                                        float m10, float m11, float cx,
                                        int base, int cg)
{
    const float STEP = 2.0f / 383.0f;
    float xs = __fadd_rn(__fmul_rn((float)j, STEP), -1.0f);

    float gx = __fadd_rn(__fmaf_rn(m01, ys, __fmul_rn(m00, xs)), cy);
    float gy = __fadd_rn(__fmaf_rn(m11, ys, __fmul_rn(m10, xs)), cx);

    float x = __fmul_rn(__fmul_rn(__fadd_rn(gx, 1.0f), 384.0f), 0.5f);
    float y = __fmul_rn(__fmul_rn(__fadd_rn(gy, 1.0f), 384.0f), 0.5f);

    int x0 = (int)floorf(x);
    int y0 = (int)floorf(y);
    int x1 = x0 + 1;
    int y1 = y0 + 1;
    x0 = min(max(x0, 0), W_ - 1);
    x1 = min(max(x1, 0), W_ - 1);
    y0 = min(max(y0, 0), H_ - 1);
    y1 = min(max(y1, 0), H_ - 1);
    float x0f = (float)x0, x1f = (float)x1;
    float y0f = (float)y0, y1f = (float)y1;

    float wxa = __fsub_rn(x1f, x);
    float wxc = __fsub_rn(x, x0f);
    float wya = __fsub_rn(y1f, y);
    float wyb = __fsub_rn(y, y0f);

    Tap t;
    t.wa = __fmul_rn(wxa, wya);
    t.wb = __fmul_rn(wxa, wyb);
    t.wc = __fmul_rn(wxc, wya);
    t.wd = __fmul_rn(wxc, wyb);
    t.ia = base + (y0 * W_ + x0) * CV_ + cg;
    t.ib = base + (y1 * W_ + x0) * CV_ + cg;
    t.ic = base + (y0 * W_ + x1) * CV_ + cg;
    t.id = base + (y1 * W_ + x1) * CV_ + cg;
    return t;
}

// blocks: B*H*(W/64) = 16*384*6 = 36864, row-major (batch, row, tile)
__global__ __launch_bounds__(256)
void st_bilinear_kernel(const float4* __restrict__ img,
                        float4* __restrict__ out)
{
    // --- theta-independent prologue (overlaps with setup kernel via PDL) ---
    const int tid = threadIdx.x;
    const int blk = blockIdx.x;

    const int tile = blk % 6;                 // 64-px column tile
    const int bi   = blk / 6;                 // b*384 + i
    const int i    = bi % H_;
    const int b    = bi / H_;

    const int j0 = tile * 64 + (tid >> 3);    // first pixel column
    const int j1 = j0 + 32;                   // second pixel column
    const int cg = tid & 7;                   // float4 channel group

    const float STEP = 2.0f / 383.0f;
    float ys = __fadd_rn(__fmul_rn((float)i, STEP), -1.0f);

    const int base = b * (H_ * W_ * CV_);

    // --- wait for setup kernel's g_coef writes ---
    asm volatile("griddepcontrol.wait;" ::: "memory");

    float m00 = g_coef[b][0], m01 = g_coef[b][1], cy = g_coef[b][2];
    float m10 = g_coef[b][3], m11 = g_coef[b][4], cx = g_coef[b][5];

    Tap t0 = make_tap(j0, ys, m00, m01, cy, m10, m11, cx, base, cg);
    Tap t1 = make_tap(j1, ys, m00, m01, cy, m10, m11, cx, base, cg);

    // 8 front-batched, fully-coalesced LDG.128 (4 pixels/warp per tap)
    float4 a0 = __ldg(img + t0.ia);
    float4 b0 = __ldg(img + t0.ib);
    float4 c0 = __ldg(img + t0.ic);
    float4 d0 = __ldg(img + t0.id);
    float4 a1 = __ldg(img + t1.ia);
    float4 b1 = __ldg(img + t1.ib);
    float4 c1 = __ldg(img + t1.ic);
    float4 d1 = __ldg(img + t1.id);

#define BLEND(T,A,B,C,D,f) \
    __fadd_rn(__fadd_rn(__fadd_rn(__fmul_rn((T).wa, (A).f), __fmul_rn((T).wb, (B).f)), \
                         __fmul_rn((T).wc, (C).f)), __fmul_rn((T).wd, (D).f))

    float4 r0, r1;
    r0.x = BLEND(t0, a0, b0, c0, d0, x);
    r0.y = BLEND(t0, a0, b0, c0, d0, y);
    r0.z = BLEND(t0, a0, b0, c0, d0, z);
    r0.w = BLEND(t0, a0, b0, c0, d0, w);
    r1.x = BLEND(t1, a1, b1, c1, d1, x);
    r1.y = BLEND(t1, a1, b1, c1, d1, y);
    r1.z = BLEND(t1, a1, b1, c1, d1, z);
    r1.w = BLEND(t1, a1, b1, c1, d1, w);
#undef BLEND

    const int orow = base + (i * W_) * CV_ + cg;
    out[orow + j0 * CV_] = r0;     // plain cached stores
    out[orow + j1 * CV_] = r1;
}

extern "C" void kernel_launch(void* const* d_in, const int* in_sizes, int n_in,
                              void* d_out, int out_size)
{
    const float4* img   = (const float4*)d_in[0];   // images: (16,384,384,32) f32
    const float*  theta = (const float*)d_in[1];    // theta:  (16,6) f32
    float4* out = (float4*)d_out;

    st_setup_kernel<<<1, 32>>>(theta);

    // Main kernel with PDL: may launch while setup is still running;
    // griddepcontrol.wait inside orders the g_coef reads.
    cudaLaunchConfig_t cfg = {};
    cfg.gridDim  = dim3(B_ * H_ * (W_ / 64));   // 36864
    cfg.blockDim = dim3(256);
    cfg.dynamicSmemBytes = 0;
    cfg.stream = 0;   // legacy default stream (capture stream)
    cudaLaunchAttribute attr[1];
    attr[0].id = cudaLaunchAttributeProgrammaticStreamSerialization;
    attr[0].val.programmaticStreamSerializationAllowed = 1;
    cfg.attrs = attr;
    cfg.numAttrs = 1;
    cudaLaunchKernelEx(&cfg, st_bilinear_kernel, img, out);
}